// round 1
// baseline (speedup 1.0000x reference)
#include <cuda_runtime.h>
#include <cstdint>

#define T_LEN 2048
#define BATCH 16
#define I_DIM 512
#define H_DIM 512
#define IH    1024

// ---------------------------------------------------------------------------
// f32x2 packed helpers (Blackwell native 2xFP32 pipe)
// ---------------------------------------------------------------------------
__device__ __forceinline__ unsigned long long f32x2_fma(unsigned long long a,
                                                        unsigned long long b,
                                                        unsigned long long c) {
    unsigned long long d;
    asm("fma.rn.f32x2 %0, %1, %2, %3;" : "=l"(d) : "l"(a), "l"(b), "l"(c));
    return d;
}

__device__ __forceinline__ uint32_t smem_u32(const void* p) {
    uint32_t a;
    asm("{ .reg .u64 t; cvta.to.shared.u64 t, %1; cvt.u32.u64 %0, t; }"
        : "=r"(a) : "l"(p));
    return a;
}

// ---------------------------------------------------------------------------
// Kernel 1: x_proj = inputs @ w_xh^T + bias, written IN-PLACE into d_out
// C[m][h] = sum_i A[m][i] * W[h][512 + i] + bias[h]
// M = 32768, N = 512, K = 512. BM=128 BN=128 BK=16, 256 thr, 8x8/thread.
// ---------------------------------------------------------------------------
__global__ void __launch_bounds__(256)
xproj_gemm(const float* __restrict__ A, const float* __restrict__ W,
           const float* __restrict__ bias, float* __restrict__ C) {
    __shared__ __align__(16) float As[16][128];
    __shared__ __align__(16) float Bs[16][128];

    const int tid = threadIdx.x;
    const int m0 = blockIdx.y * 128;
    const int n0 = blockIdx.x * 128;
    const int tx = tid & 15;       // 0..15  -> n
    const int ty = tid >> 4;       // 0..15  -> m
    const int lr = tid >> 2;       // 0..63  loader row
    const int lc = (tid & 3) * 4;  // 0,4,8,12 loader col (k)

    float acc[8][8];
#pragma unroll
    for (int i = 0; i < 8; i++)
#pragma unroll
        for (int j = 0; j < 8; j++) acc[i][j] = 0.f;

    for (int k0 = 0; k0 < 512; k0 += 16) {
#pragma unroll
        for (int s = 0; s < 2; s++) {
            int row = lr + s * 64;
            float4 va = *(const float4*)(A + (size_t)(m0 + row) * 512 + k0 + lc);
            As[lc + 0][row] = va.x; As[lc + 1][row] = va.y;
            As[lc + 2][row] = va.z; As[lc + 3][row] = va.w;
            float4 vb = *(const float4*)(W + (size_t)(n0 + row) * IH + 512 + k0 + lc);
            Bs[lc + 0][row] = vb.x; Bs[lc + 1][row] = vb.y;
            Bs[lc + 2][row] = vb.z; Bs[lc + 3][row] = vb.w;
        }
        __syncthreads();

#pragma unroll
        for (int kk = 0; kk < 16; kk++) {
            float4 a0 = *(const float4*)&As[kk][ty * 8];
            float4 a1 = *(const float4*)&As[kk][ty * 8 + 4];
            float4 b0 = *(const float4*)&Bs[kk][tx * 8];
            float4 b1 = *(const float4*)&Bs[kk][tx * 8 + 4];
            float af[8] = {a0.x, a0.y, a0.z, a0.w, a1.x, a1.y, a1.z, a1.w};
            float bf[8] = {b0.x, b0.y, b0.z, b0.w, b1.x, b1.y, b1.z, b1.w};
#pragma unroll
            for (int i = 0; i < 8; i++)
#pragma unroll
                for (int j = 0; j < 8; j++) acc[i][j] = fmaf(af[i], bf[j], acc[i][j]);
        }
        __syncthreads();
    }

    float bj[8];
#pragma unroll
    for (int j = 0; j < 8; j++) bj[j] = bias[n0 + tx * 8 + j];

#pragma unroll
    for (int i = 0; i < 8; i++) {
        int row = m0 + ty * 8 + i;
        float4 v0, v1;
        v0.x = acc[i][0] + bj[0]; v0.y = acc[i][1] + bj[1];
        v0.z = acc[i][2] + bj[2]; v0.w = acc[i][3] + bj[3];
        v1.x = acc[i][4] + bj[4]; v1.y = acc[i][5] + bj[5];
        v1.z = acc[i][6] + bj[6]; v1.w = acc[i][7] + bj[7];
        float4* cp = (float4*)(C + (size_t)row * 512 + n0 + tx * 8);
        cp[0] = v0;
        cp[1] = v1;
    }
}

// ---------------------------------------------------------------------------
// Kernel 2: sequential scan, one 8-CTA cluster per batch element.
// CTA = (batch b, k-group kg): owns output rows k in [kg*64, kg*64+64).
// Weight slice 64x512 fp32 held in REGISTERS (64 f32x2 per thread).
// h (512 fp32) replicated in every CTA's SMEM, double-buffered; new fragments
// broadcast via DSMEM st.shared::cluster; cluster barrier per step.
// x_proj is read from (and h written back to) d_out in place.
// ---------------------------------------------------------------------------
__global__ void __cluster_dims__(8, 1, 1) __launch_bounds__(256, 1)
rnn_scan(const float* __restrict__ state, const float* __restrict__ W,
         float* __restrict__ outp, float* __restrict__ lastp) {
    __shared__ __align__(16) float h_buf[2][512];

    const int tid = threadIdx.x;
    const int cta = blockIdx.x;
    const int b   = cta >> 3;   // batch
    const int kg  = cta & 7;    // k-group (== cluster rank)
    const int o   = tid >> 2;   // 0..63 local output
    const int sub = tid & 3;    // 0..3 partial-dot slice
    const int k   = kg * 64 + o;

    // Load this thread's 128 weights (w_hh[k][sub*128 .. +128)) as 64 f32x2.
    unsigned long long w[64];
    {
        const unsigned long long* wp =
            (const unsigned long long*)(W + (size_t)k * IH + sub * 128);
#pragma unroll
        for (int i = 0; i < 64; i++) w[i] = wp[i];
    }

    // Init h buffer 0 with initial state (replicated per CTA).
    for (int j = tid; j < 512; j += 256) h_buf[0][j] = state[b * 512 + j];
    __syncthreads();

    const uint32_t hb0 = smem_u32(&h_buf[0][0]);
    const uint32_t hb1 = smem_u32(&h_buf[1][0]);

    size_t idx = ((size_t)b) * 512 + k;          // t = 0; stride 8192 per t
    float xp_cur = (sub == 0) ? outp[idx] : 0.f;
    int cur = 0;

    for (int t = 0; t < T_LEN; t++) {
        // Prefetch next step's x_proj (its slot is not overwritten until t+1).
        float xp_next = 0.f;
        if (sub == 0 && t + 1 < T_LEN) xp_next = __ldg(outp + idx + 8192);

        // Partial dot: 128 MACs as 64 packed f32x2 FMAs, h loaded as LDS.128.
        const ulonglong2* hp =
            (const ulonglong2*)&h_buf[cur][sub * 128];
        unsigned long long acc = 0ull;  // bit pattern of {0.f, 0.f}
#pragma unroll
        for (int jj = 0; jj < 32; jj++) {
            ulonglong2 hv = hp[jj];
            acc = f32x2_fma(w[2 * jj], hv.x, acc);
            acc = f32x2_fma(w[2 * jj + 1], hv.y, acc);
        }
        float lo, hi;
        asm("mov.b64 {%0, %1}, %2;" : "=f"(lo), "=f"(hi) : "l"(acc));
        float a = lo + hi;
        a += __shfl_xor_sync(0xffffffffu, a, 1);
        a += __shfl_xor_sync(0xffffffffu, a, 2);

        if (sub == 0) {
            float val = a + xp_cur;
            outp[idx] = val;                      // outputs[t] = h_t (in place)
            if (t == T_LEN - 1) lastp[b * 512 + k] = val;
            // Broadcast h_t[k] into next-phase buffer of all 8 cluster CTAs.
            uint32_t laddr = (cur ? hb0 : hb1) + (uint32_t)(k * 4);
#pragma unroll
            for (int r = 0; r < 8; r++) {
                uint32_t raddr;
                asm volatile("mapa.shared::cluster.u32 %0, %1, %2;"
                             : "=r"(raddr) : "r"(laddr), "r"(r));
                asm volatile("st.shared::cluster.f32 [%0], %1;"
                             :: "r"(raddr), "f"(val) : "memory");
            }
        }
        // Cluster barrier: release DSMEM stores, acquire before next read.
        asm volatile("barrier.cluster.arrive.aligned;" ::: "memory");
        asm volatile("barrier.cluster.wait.aligned;" ::: "memory");

        xp_cur = xp_next;
        cur ^= 1;
        idx += 8192;
    }
}

// ---------------------------------------------------------------------------
extern "C" void kernel_launch(void* const* d_in, const int* in_sizes, int n_in,
                              void* d_out, int out_size) {
    const float* inputs = (const float*)d_in[0];  // (T, B, I)
    const float* state  = (const float*)d_in[1];  // (B, H)
    const float* weight = (const float*)d_in[2];  // (H, I+H)
    const float* bias   = (const float*)d_in[3];  // (H,)
    float* outp  = (float*)d_out;                           // (T, B, H)
    float* lastp = outp + (size_t)T_LEN * BATCH * H_DIM;    // (B, H)

    dim3 ggrid(512 / 128, (T_LEN * BATCH) / 128);  // (4, 256)
    xproj_gemm<<<ggrid, 256>>>(inputs, weight, bias, outp);

    rnn_scan<<<BATCH * 8, 256>>>(state, weight, outp, lastp);
}

// round 2
// speedup vs baseline: 1.1427x; 1.1427x over previous
#include <cuda_runtime.h>
#include <cstdint>

#define T_LEN 2048
#define BATCH 16
#define I_DIM 512
#define H_DIM 512
#define IH    1024

typedef unsigned long long ull;

// ---------------------------------------------------------------------------
// f32x2 packed helpers (Blackwell native 2xFP32 pipe)
// ---------------------------------------------------------------------------
__device__ __forceinline__ ull f32x2_fma(ull a, ull b, ull c) {
    ull d;
    asm("fma.rn.f32x2 %0, %1, %2, %3;" : "=l"(d) : "l"(a), "l"(b), "l"(c));
    return d;
}
__device__ __forceinline__ ull f32x2_add(ull a, ull b) {
    ull d;
    asm("add.rn.f32x2 %0, %1, %2;" : "=l"(d) : "l"(a), "l"(b));
    return d;
}
__device__ __forceinline__ uint32_t smem_u32(const void* p) {
    uint32_t a;
    asm("{ .reg .u64 t; cvta.to.shared.u64 t, %1; cvt.u32.u64 %0, t; }"
        : "=r"(a) : "l"(p));
    return a;
}
__device__ __forceinline__ uint32_t mapa_u32(uint32_t laddr, uint32_t rank) {
    uint32_t r;
    asm("mapa.shared::cluster.u32 %0, %1, %2;" : "=r"(r) : "r"(laddr), "r"(rank));
    return r;
}
__device__ __forceinline__ void mbar_init(uint32_t mb, uint32_t cnt) {
    asm volatile("mbarrier.init.shared.b64 [%0], %1;" :: "r"(mb), "r"(cnt) : "memory");
}
__device__ __forceinline__ void mbar_arrive_expect_tx(uint32_t mb, uint32_t bytes) {
    asm volatile("mbarrier.arrive.expect_tx.shared.b64 _, [%0], %1;"
                 :: "r"(mb), "r"(bytes) : "memory");
}
__device__ __forceinline__ void mbar_wait(uint32_t mb, uint32_t parity) {
    uint32_t done;
    asm volatile(
        "{\n\t.reg .pred p;\n\t"
        "mbarrier.try_wait.parity.acquire.cta.shared::cta.b64 p, [%1], %2;\n\t"
        "selp.b32 %0, 1, 0, p;\n\t}"
        : "=r"(done) : "r"(mb), "r"(parity) : "memory");
    if (!done) {
        asm volatile(
            "{\n\t.reg .pred P1;\n\t"
            "WAIT_LOOP_%=:\n\t"
            "mbarrier.try_wait.parity.acquire.cta.shared::cta.b64 P1, [%0], %1, 0x989680;\n\t"
            "@P1 bra.uni WAIT_DONE_%=;\n\t"
            "bra.uni WAIT_LOOP_%=;\n\t"
            "WAIT_DONE_%=:\n\t}"
            :: "r"(mb), "r"(parity) : "memory");
    }
}
__device__ __forceinline__ void st_async_remote(uint32_t raddr, uint32_t bits,
                                                uint32_t rmbar) {
    asm volatile(
        "st.async.shared::cluster.mbarrier::complete_tx::bytes.b32 [%0], %1, [%2];"
        :: "r"(raddr), "r"(bits), "r"(rmbar) : "memory");
}

// ---------------------------------------------------------------------------
// Kernel 1: x_proj = inputs @ w_xh^T + bias, written IN-PLACE into d_out
// ---------------------------------------------------------------------------
__global__ void __launch_bounds__(256)
xproj_gemm(const float* __restrict__ A, const float* __restrict__ W,
           const float* __restrict__ bias, float* __restrict__ C) {
    __shared__ __align__(16) float As[16][128];
    __shared__ __align__(16) float Bs[16][128];

    const int tid = threadIdx.x;
    const int m0 = blockIdx.y * 128;
    const int n0 = blockIdx.x * 128;
    const int tx = tid & 15;
    const int ty = tid >> 4;
    const int lr = tid >> 2;
    const int lc = (tid & 3) * 4;

    float acc[8][8];
#pragma unroll
    for (int i = 0; i < 8; i++)
#pragma unroll
        for (int j = 0; j < 8; j++) acc[i][j] = 0.f;

    for (int k0 = 0; k0 < 512; k0 += 16) {
#pragma unroll
        for (int s = 0; s < 2; s++) {
            int row = lr + s * 64;
            float4 va = *(const float4*)(A + (size_t)(m0 + row) * 512 + k0 + lc);
            As[lc + 0][row] = va.x; As[lc + 1][row] = va.y;
            As[lc + 2][row] = va.z; As[lc + 3][row] = va.w;
            float4 vb = *(const float4*)(W + (size_t)(n0 + row) * IH + 512 + k0 + lc);
            Bs[lc + 0][row] = vb.x; Bs[lc + 1][row] = vb.y;
            Bs[lc + 2][row] = vb.z; Bs[lc + 3][row] = vb.w;
        }
        __syncthreads();

#pragma unroll
        for (int kk = 0; kk < 16; kk++) {
            float4 a0 = *(const float4*)&As[kk][ty * 8];
            float4 a1 = *(const float4*)&As[kk][ty * 8 + 4];
            float4 b0 = *(const float4*)&Bs[kk][tx * 8];
            float4 b1 = *(const float4*)&Bs[kk][tx * 8 + 4];
            float af[8] = {a0.x, a0.y, a0.z, a0.w, a1.x, a1.y, a1.z, a1.w};
            float bf[8] = {b0.x, b0.y, b0.z, b0.w, b1.x, b1.y, b1.z, b1.w};
#pragma unroll
            for (int i = 0; i < 8; i++)
#pragma unroll
                for (int j = 0; j < 8; j++) acc[i][j] = fmaf(af[i], bf[j], acc[i][j]);
        }
        __syncthreads();
    }

    float bj[8];
#pragma unroll
    for (int j = 0; j < 8; j++) bj[j] = bias[n0 + tx * 8 + j];

#pragma unroll
    for (int i = 0; i < 8; i++) {
        int row = m0 + ty * 8 + i;
        float4 v0, v1;
        v0.x = acc[i][0] + bj[0]; v0.y = acc[i][1] + bj[1];
        v0.z = acc[i][2] + bj[2]; v0.w = acc[i][3] + bj[3];
        v1.x = acc[i][4] + bj[4]; v1.y = acc[i][5] + bj[5];
        v1.z = acc[i][6] + bj[6]; v1.w = acc[i][7] + bj[7];
        float4* cp = (float4*)(C + (size_t)row * 512 + n0 + tx * 8);
        cp[0] = v0;
        cp[1] = v1;
    }
}

// ---------------------------------------------------------------------------
// Kernel 2: sequential scan. 8-CTA cluster per batch. Weights in registers.
// Cross-CTA h broadcast via st.async + mbarrier complete_tx (no cluster
// barrier, no L1 flush, no fences on the per-step path).
// ---------------------------------------------------------------------------
__global__ void __cluster_dims__(8, 1, 1) __launch_bounds__(256, 1)
rnn_scan(const float* __restrict__ state, const float* __restrict__ W,
         float* __restrict__ outp, float* __restrict__ lastp) {
    __shared__ __align__(16) float h_buf[2][512];
    __shared__ __align__(8) ull mbar[2];

    const int tid = threadIdx.x;
    const int cta = blockIdx.x;
    const int b   = cta >> 3;
    const int kg  = cta & 7;
    const int o   = tid >> 2;   // 0..63 local output row
    const int sub = tid & 3;    // 0..3 k-slice
    const int k   = kg * 64 + o;

    // 128 weights per thread in registers (64 packed f32x2).
    ull w[64];
    {
        const ull* wp = (const ull*)(W + (size_t)k * IH + sub * 128);
#pragma unroll
        for (int i = 0; i < 64; i++) w[i] = wp[i];
    }

    for (int j = tid; j < 512; j += 256) h_buf[0][j] = state[b * 512 + j];

    const uint32_t mb0 = smem_u32(&mbar[0]);
    const uint32_t mb1 = smem_u32(&mbar[1]);
    if (tid == 0) {
        mbar_init(mb0, 1);
        mbar_init(mb1, 1);
        mbar_arrive_expect_tx(mb0, 2048);  // first use: receive t=2 fragments
        mbar_arrive_expect_tx(mb1, 2048);  // first use: receive t=1 fragments
    }
    __syncthreads();
    // Cluster entry barrier: mbarriers must be live before any peer st.async.
    asm volatile("barrier.cluster.arrive.aligned;" ::: "memory");
    asm volatile("barrier.cluster.wait.aligned;" ::: "memory");

    // Precompute remote addresses (this thread's h slot + mbar, per rank/buffer).
    const uint32_t d0 = smem_u32(&h_buf[0][k]);
    const uint32_t d1 = smem_u32(&h_buf[1][k]);
    uint32_t rdst0[8], rdst1[8], rmb0[8], rmb1[8];
#pragma unroll
    for (int r = 0; r < 8; r++) {
        rdst0[r] = mapa_u32(d0, r);
        rdst1[r] = mapa_u32(d1, r);
        rmb0[r]  = mapa_u32(mb0, r);
        rmb1[r]  = mapa_u32(mb1, r);
    }

    size_t idx = ((size_t)b) * 512 + k;
    float xp_cur = (sub == 0) ? outp[idx] : 0.f;
    uint32_t par0 = 0, par1 = 0;

#define RNN_STEP(CUR, TT, MB_L, PAR, RDST, RMB)                                 \
    do {                                                                        \
        if ((TT) > 0) {                                                         \
            mbar_wait(MB_L, PAR);                                               \
            PAR ^= 1;                                                           \
            if (tid == 0 && (TT) + 2 < T_LEN)                                   \
                mbar_arrive_expect_tx(MB_L, 2048);                              \
        }                                                                       \
        float xp_next = 0.f;                                                    \
        if (sub == 0 && (TT) + 1 < T_LEN) xp_next = __ldg(outp + idx + 8192);   \
        const ulonglong2* hp = (const ulonglong2*)&h_buf[CUR][sub * 128];       \
        ull a0 = 0ull, a1 = 0ull, a2 = 0ull, a3 = 0ull;                         \
        _Pragma("unroll")                                                       \
        for (int jj = 0; jj < 8; jj++) {                                        \
            ulonglong2 v0 = hp[4 * jj + 0];                                     \
            ulonglong2 v1 = hp[4 * jj + 1];                                     \
            ulonglong2 v2 = hp[4 * jj + 2];                                     \
            ulonglong2 v3 = hp[4 * jj + 3];                                     \
            a0 = f32x2_fma(w[8 * jj + 0], v0.x, a0);                            \
            a1 = f32x2_fma(w[8 * jj + 1], v0.y, a1);                            \
            a2 = f32x2_fma(w[8 * jj + 2], v1.x, a2);                            \
            a3 = f32x2_fma(w[8 * jj + 3], v1.y, a3);                            \
            a0 = f32x2_fma(w[8 * jj + 4], v2.x, a0);                            \
            a1 = f32x2_fma(w[8 * jj + 5], v2.y, a1);                            \
            a2 = f32x2_fma(w[8 * jj + 6], v3.x, a2);                            \
            a3 = f32x2_fma(w[8 * jj + 7], v3.y, a3);                            \
        }                                                                       \
        ull s = f32x2_add(f32x2_add(a0, a1), f32x2_add(a2, a3));                \
        float lo, hi;                                                           \
        asm("mov.b64 {%0, %1}, %2;" : "=f"(lo), "=f"(hi) : "l"(s));             \
        float a = lo + hi;                                                      \
        a += __shfl_xor_sync(0xffffffffu, a, 1);                                \
        a += __shfl_xor_sync(0xffffffffu, a, 2);                                \
        if (sub == 0) {                                                         \
            float val = a + xp_cur;                                             \
            outp[idx] = val;                                                    \
            if ((TT) == T_LEN - 1) {                                            \
                lastp[b * 512 + k] = val;                                       \
            } else {                                                            \
                uint32_t vb = __float_as_uint(val);                             \
                _Pragma("unroll")                                               \
                for (int r = 0; r < 8; r++)                                     \
                    st_async_remote(RDST[r], vb, RMB[r]);                       \
            }                                                                   \
        }                                                                       \
        xp_cur = xp_next;                                                       \
        idx += 8192;                                                            \
    } while (0)

    for (int t = 0; t < T_LEN; t += 2) {
        RNN_STEP(0, t,     mb0, par0, rdst1, rmb1);  // reads buf0, sends buf1
        RNN_STEP(1, t + 1, mb1, par1, rdst0, rmb0);  // reads buf1, sends buf0
    }
#undef RNN_STEP

    // Keep CTAs alive until all in-flight remote stores have landed.
    asm volatile("barrier.cluster.arrive.aligned;" ::: "memory");
    asm volatile("barrier.cluster.wait.aligned;" ::: "memory");
}

// ---------------------------------------------------------------------------
extern "C" void kernel_launch(void* const* d_in, const int* in_sizes, int n_in,
                              void* d_out, int out_size) {
    const float* inputs = (const float*)d_in[0];  // (T, B, I)
    const float* state  = (const float*)d_in[1];  // (B, H)
    const float* weight = (const float*)d_in[2];  // (H, I+H)
    const float* bias   = (const float*)d_in[3];  // (H,)
    float* outp  = (float*)d_out;                          // (T, B, H)
    float* lastp = outp + (size_t)T_LEN * BATCH * H_DIM;   // (B, H)

    dim3 ggrid(512 / 128, (T_LEN * BATCH) / 128);
    xproj_gemm<<<ggrid, 256>>>(inputs, weight, bias, outp);

    rnn_scan<<<BATCH * 8, 256>>>(state, weight, outp, lastp);
}